// round 1
// baseline (speedup 1.0000x reference)
#include <cuda_runtime.h>
#include <cuda_bf16.h>

// AlltoAll2D: output[r] is the concatenation over source ranks s of
// input[s][in_off[s][r] : in_off[s][r]+splits[s][r]], rows past the total zeroed.
//
// Strategy: tiny setup kernel (1 thread) computes per-(r,s) metadata so the
// gather kernel needs only: find s via linear scan of 8 cum values, then
// src_flat_row = j + add[r][s]. One block per output row, one float4 per thread.

#define MAXW 64

__device__ int       g_cum[MAXW * MAXW];     // inclusive cumsum over s of recv[r][s]
__device__ long long g_add[MAXW * MAXW];     // s*M + in_off[s][r] - out_off[r][s]
__device__ int       g_total[MAXW];          // total valid rows for rank r

__global__ void setup_kernel(const int* __restrict__ splits, int W, int M) {
    // Single-thread: O(W^3) = 512 int ops for W=8.
    if (threadIdx.x != 0 || blockIdx.x != 0) return;
    for (int r = 0; r < W; ++r) {
        int c = 0;
        for (int s = 0; s < W; ++s) {
            int recv = splits[s * W + r];          // rows r receives from s
            int ioff = 0;                           // in_off[s][r]
            for (int rr = 0; rr < r; ++rr) ioff += splits[s * W + rr];
            int out_off = c;                        // exclusive prefix = chunk start in output[r]
            c += recv;
            g_cum[r * W + s] = c;
            g_add[r * W + s] = (long long)s * M + ioff - out_off;
        }
        g_total[r] = c;
    }
}

__global__ void gather_kernel(const float4* __restrict__ in,
                              float4* __restrict__ out,
                              int W, int M, int H4) {
    const int row = blockIdx.x;                // r * M + j
    const int r = row / M;
    const int j = row - r * M;

    float4* dst = out + (size_t)row * H4;

    if (j >= g_total[r]) {
        // invalid tail row: zero-fill (d_out is poisoned before timing)
        const float4 z = make_float4(0.f, 0.f, 0.f, 0.f);
        for (int t = threadIdx.x; t < H4; t += blockDim.x) dst[t] = z;
        return;
    }

    // find source rank s: first s with cum[r][s] > j (W small, linear scan)
    int s = 0;
    const int base = r * W;
    while (g_cum[base + s] <= j) ++s;

    const long long src_row = (long long)j + g_add[base + s];
    const float4* src = in + src_row * (long long)H4;

    for (int t = threadIdx.x; t < H4; t += blockDim.x) dst[t] = src[t];
}

extern "C" void kernel_launch(void* const* d_in, const int* in_sizes, int n_in,
                              void* d_out, int out_size) {
    const float* input  = (const float*)d_in[0];
    const int*   splits = (const int*)d_in[1];
    // d_in[2] = num_sm: only a tuning hint, ignored.

    // Recover shapes: in_sizes[1] = W*W; H fixed at 1024 per problem spec.
    int W = 1;
    {
        int ww = in_sizes[1];
        while (W * W < ww) ++W;
    }
    const int H = 1024;
    const int M = (int)((long long)in_sizes[0] / ((long long)W * H));
    const int H4 = H / 4;

    setup_kernel<<<1, 1>>>(splits, W, M);

    const int rows = W * M;
    gather_kernel<<<rows, 256>>>((const float4*)input, (float4*)d_out, W, M, H4);
}

// round 9
// speedup vs baseline: 1.4367x; 1.4367x over previous
#include <cuda_runtime.h>
#include <cuda_bf16.h>

// AlltoAll2D: output[r] = concat over s of input[s][in_off[s][r] : +splits[s][r]],
// rows past the total zeroed. Pure row gather: 4KB rows, fp32.
//
// 3-phase:
//  1. setup_kernel (1 thread): cum / add / total metadata (O(W^3), W=8).
//  2. rowmap_kernel: per output row, resolve source flat row (or -1 invalid).
//  3. gather_kernel: 8 rows per block, 8 independent LDG.128 per thread (MLP=8),
//     streaming loads/stores (__ldcs/__stcs) since data has zero reuse.

#define MAXW 64
#define MAXROWS (1 << 22)   // 4M rows max (16 MB static map)
#define RPB 8               // rows per block

__device__ int g_cum[MAXW * MAXW];    // inclusive cumsum over s of recv[r][s]
__device__ int g_add[MAXW * MAXW];    // s*M + in_off[s][r] - out_off[r][s]
__device__ int g_total[MAXW];         // total valid rows for rank r
__device__ int g_map[MAXROWS];        // src flat row per output row, -1 = invalid

__global__ void setup_kernel(const int* __restrict__ splits, int W, int M) {
    if (threadIdx.x != 0 || blockIdx.x != 0) return;
    for (int r = 0; r < W; ++r) {
        int c = 0;
        for (int s = 0; s < W; ++s) {
            int recv = splits[s * W + r];
            int ioff = 0;
            for (int rr = 0; rr < r; ++rr) ioff += splits[s * W + rr];
            int out_off = c;
            c += recv;
            g_cum[r * W + s] = c;
            g_add[r * W + s] = s * M + ioff - out_off;
        }
        g_total[r] = c;
    }
}

__global__ void rowmap_kernel(int W, int M, int rows) {
    int row = blockIdx.x * blockDim.x + threadIdx.x;
    if (row >= rows) return;
    int r = row / M;
    int j = row - r * M;
    if (j >= g_total[r]) { g_map[row] = -1; return; }
    int base = r * W;
    int s = 0;
    while (g_cum[base + s] <= j) ++s;
    g_map[row] = j + g_add[base + s];
}

__global__ void __launch_bounds__(256) gather_kernel(const float4* __restrict__ in,
                                                     float4* __restrict__ out,
                                                     int H4, int rows) {
    const int row0 = blockIdx.x * RPB;

    int m[RPB];
#pragma unroll
    for (int k = 0; k < RPB; ++k) {
        int row = row0 + k;
        m[k] = (row < rows) ? g_map[row] : -2;   // -2: past end, skip store too
    }

    if (H4 == 256 && blockDim.x == 256) {
        // Fast path: exactly one float4 column per thread; 8 independent loads
        // front-batched (MLP=8), then 8 stores.
        const int c = threadIdx.x;
        float4 v[RPB];
#pragma unroll
        for (int k = 0; k < RPB; ++k) {
            if (m[k] >= 0)
                v[k] = __ldcs(in + (long long)m[k] * 256 + c);
            else
                v[k] = make_float4(0.f, 0.f, 0.f, 0.f);
        }
#pragma unroll
        for (int k = 0; k < RPB; ++k) {
            if (m[k] != -2)
                __stcs(out + (long long)(row0 + k) * 256 + c, v[k]);
        }
        return;
    }

    for (int c = threadIdx.x; c < H4; c += blockDim.x) {
        float4 v[RPB];
#pragma unroll
        for (int k = 0; k < RPB; ++k) {
            if (m[k] >= 0)
                v[k] = __ldcs(in + (long long)m[k] * H4 + c);
            else
                v[k] = make_float4(0.f, 0.f, 0.f, 0.f);
        }
#pragma unroll
        for (int k = 0; k < RPB; ++k) {
            if (m[k] != -2)
                __stcs(out + (long long)(row0 + k) * H4 + c, v[k]);
        }
    }
}

extern "C" void kernel_launch(void* const* d_in, const int* in_sizes, int n_in,
                              void* d_out, int out_size) {
    const float* input  = (const float*)d_in[0];
    const int*   splits = (const int*)d_in[1];
    // d_in[2] = num_sm: tuning hint only, ignored.

    int W = 1;
    { int ww = in_sizes[1]; while (W * W < ww) ++W; }
    const int H = 1024;
    const int M = (int)((long long)in_sizes[0] / ((long long)W * H));
    const int H4 = H / 4;
    const int rows = W * M;

    setup_kernel<<<1, 1>>>(splits, W, M);
    rowmap_kernel<<<(rows + 255) / 256, 256>>>(W, M, rows);
    gather_kernel<<<(rows + RPB - 1) / RPB, 256>>>((const float4*)input,
                                                   (float4*)d_out, H4, rows);
}